// round 1
// baseline (speedup 1.0000x reference)
#include <cuda_runtime.h>
#include <math.h>

// Problem constants (fixed by the dataset)
#define BATCH 4
#define TSEQ  2048
#define CDIM  1024
#define NH    16
#define DH    64
#define BT    (BATCH * TSEQ)   // 8192 rows
#define BH    (BATCH * NH)     // 64 (batch*heads)

// ---------------------------------------------------------------------------
// Scratch (device globals; no allocation allowed in kernel_launch)
// ---------------------------------------------------------------------------
__device__ float g_qkv[(size_t)BT * 3 * CDIM];       // 96 MB   x @ Wqkv^T
__device__ float g_Qh[(size_t)BH * TSEQ * DH];       // 32 MB   [bh][t][d], rope'd, *0.125
__device__ float g_Kh[(size_t)BH * TSEQ * DH];       // 32 MB   [bh][t][d], rope'd
__device__ float g_Vh[(size_t)BH * TSEQ * DH];       // 32 MB   [bh][t][d]
__device__ float g_Oh[(size_t)BT * CDIM];            // 32 MB   attention out, [b*T+t][h*64+d]
__device__ float g_cosT[TSEQ * (DH / 2)];            // rope tables
__device__ float g_sinT[TSEQ * (DH / 2)];

// ---------------------------------------------------------------------------
// RoPE tables. Match JAX fp32 semantics: theta rounded to fp32, angle = fp32
// product (same rounding as jnp.outer in fp32), then evaluate cos/sin of that
// *rounded* angle in double for accuracy.
// ---------------------------------------------------------------------------
__global__ void build_tables_kernel() {
    int idx = blockIdx.x * blockDim.x + threadIdx.x;     // t*32 + i
    if (idx >= TSEQ * (DH / 2)) return;
    int t = idx >> 5;
    int i = idx & 31;
    float theta_f = (float)pow(10000.0, -(double)(2 * i) / (double)DH);
    float angle_f = (float)t * theta_f;                  // fp32 rounding like the ref
    g_cosT[idx] = (float)cos((double)angle_f);
    g_sinT[idx] = (float)sin((double)angle_f);
}

// ---------------------------------------------------------------------------
// Generic NT GEMM: C[M,N] = A[M,K] * B[N,K]^T, all row-major, K contiguous.
// 128x128 tile, BK=16, 256 threads, 8x8 per-thread microtile.
// M%128==0, N%128==0, K%16==0 hold for every call here.
// ---------------------------------------------------------------------------
__global__ __launch_bounds__(256) void gemm_nt_kernel(
    const float* __restrict__ A, const float* __restrict__ B,
    float* __restrict__ C, int M, int N, int K)
{
    __shared__ float As[16][128];
    __shared__ float Bs[16][128];

    const int tid = threadIdx.x;
    const int tx = tid & 15;          // 0..15 -> 8 output cols each
    const int ty = tid >> 4;          // 0..15 -> 8 output rows each
    const int bm = blockIdx.y * 128;
    const int bn = blockIdx.x * 128;

    const float* Ab = A + (size_t)bm * K;
    const float* Bb = B + (size_t)bn * K;

    float acc[8][8] = {};

    for (int k0 = 0; k0 < K; k0 += 16) {
#pragma unroll
        for (int i = 0; i < 2; i++) {
            int idx = tid + i * 256;          // 0..511 float4 slots
            int m = idx >> 2;                 // tile row 0..127
            int q = idx & 3;                  // which float4 of the 16 k's
            float4 va = *(const float4*)(Ab + (size_t)m * K + k0 + q * 4);
            As[q * 4 + 0][m] = va.x; As[q * 4 + 1][m] = va.y;
            As[q * 4 + 2][m] = va.z; As[q * 4 + 3][m] = va.w;
            float4 vb = *(const float4*)(Bb + (size_t)m * K + k0 + q * 4);
            Bs[q * 4 + 0][m] = vb.x; Bs[q * 4 + 1][m] = vb.y;
            Bs[q * 4 + 2][m] = vb.z; Bs[q * 4 + 3][m] = vb.w;
        }
        __syncthreads();

#pragma unroll
        for (int k = 0; k < 16; k++) {
            float4 a0 = *(const float4*)&As[k][ty * 8];
            float4 a1 = *(const float4*)&As[k][ty * 8 + 4];
            float4 b0 = *(const float4*)&Bs[k][tx * 8];
            float4 b1 = *(const float4*)&Bs[k][tx * 8 + 4];
            float a[8] = {a0.x, a0.y, a0.z, a0.w, a1.x, a1.y, a1.z, a1.w};
            float b[8] = {b0.x, b0.y, b0.z, b0.w, b1.x, b1.y, b1.z, b1.w};
#pragma unroll
            for (int i = 0; i < 8; i++)
#pragma unroll
                for (int j = 0; j < 8; j++)
                    acc[i][j] = fmaf(a[i], b[j], acc[i][j]);
        }
        __syncthreads();
    }

#pragma unroll
    for (int i = 0; i < 8; i++) {
        float* Crow = C + (size_t)(bm + ty * 8 + i) * N + bn + tx * 8;
        *(float4*)(Crow)     = make_float4(acc[i][0], acc[i][1], acc[i][2], acc[i][3]);
        *(float4*)(Crow + 4) = make_float4(acc[i][4], acc[i][5], acc[i][6], acc[i][7]);
    }
}

// ---------------------------------------------------------------------------
// RoPE + head split. g_qkv row = b*T+t holds [3][16][64]. Writes Q,K,V in
// [bh][t][d] layout; rope on q,k; q additionally scaled by 1/sqrt(64).
// ---------------------------------------------------------------------------
__global__ __launch_bounds__(256) void rope_split_kernel() {
    const int row = blockIdx.x;                  // b*T + t
    const int b = row >> 11;
    const int t = row & (TSEQ - 1);
    const float* src = g_qkv + (size_t)row * (3 * CDIM);

    for (int p = threadIdx.x; p < 3 * CDIM / 2; p += blockDim.x) {
        int col = p * 2;
        int s = col >> 10;                       // 0=q 1=k 2=v
        int within = col & (CDIM - 1);
        int h = within >> 6;
        int j = within & (DH - 1);               // even
        float2 xv = *(const float2*)(src + col);
        size_t dst = (((size_t)(b * NH + h) * TSEQ) + t) * DH + j;
        if (s == 2) {
            *(float2*)(g_Vh + dst) = xv;
        } else {
            float c = g_cosT[t * 32 + (j >> 1)];
            float sn = g_sinT[t * 32 + (j >> 1)];
            float o0 = xv.x * c - xv.y * sn;
            float o1 = xv.y * c + xv.x * sn;
            if (s == 0) {
                o0 *= 0.125f; o1 *= 0.125f;      // 1/sqrt(d_head) folded into Q
                *(float2*)(g_Qh + dst) = make_float2(o0, o1);
            } else {
                *(float2*)(g_Kh + dst) = make_float2(o0, o1);
            }
        }
    }
}

// ---------------------------------------------------------------------------
// Flash attention, fp32, causal. 64 q-rows per CTA, 64-key tiles, online
// softmax. 256 threads; thread (ty,tx) owns a 4x4 microtile (rows ty*4..,
// cols tx*4..). Row stats reduced over the 16 threads sharing ty (shfl).
// Output written directly in [b*T+t][h*64+d] layout for the out-proj GEMM.
// ---------------------------------------------------------------------------
#define AST 68   // padded smem row stride (68*4B is 16B-aligned)

__global__ __launch_bounds__(256) void attn_kernel() {
    extern __shared__ float sm[];
    float* Qt = sm;                 // [d][r]  (transposed)
    float* Kt = Qt + 64 * AST;      // [d][c]  (transposed)
    float* Vs = Kt + 64 * AST;      // [k][d]  (natural)
    float* Ps = Vs + 64 * AST;      // [r][c]

    const int tid = threadIdx.x;
    const int tx = tid & 15;
    const int ty = tid >> 4;
    const int r0 = ty * 4;
    const int c0 = tx * 4;
    const int iq = blockIdx.x;      // q tile index (row block)
    const int bh = blockIdx.y;      // batch*head

    const float* Qg = g_Qh + ((size_t)bh * TSEQ + iq * 64) * DH;
    const float* Kg = g_Kh + (size_t)bh * TSEQ * DH;
    const float* Vg = g_Vh + (size_t)bh * TSEQ * DH;

    // Load Q tile transposed
#pragma unroll
    for (int i = 0; i < 4; i++) {
        int idx = tid + i * 256;     // 1024 float4 slots
        int r = idx >> 4;
        int q = idx & 15;
        float4 v = *(const float4*)(Qg + r * DH + q * 4);
        Qt[(q * 4 + 0) * AST + r] = v.x;
        Qt[(q * 4 + 1) * AST + r] = v.y;
        Qt[(q * 4 + 2) * AST + r] = v.z;
        Qt[(q * 4 + 3) * AST + r] = v.w;
    }

    float o[4][4] = {};
    float mi[4] = {-INFINITY, -INFINITY, -INFINITY, -INFINITY};
    float li[4] = {0.f, 0.f, 0.f, 0.f};

    for (int j = 0; j <= iq; j++) {
        __syncthreads();   // prior PV done before we overwrite Kt/Vs/Ps
#pragma unroll
        for (int i = 0; i < 4; i++) {
            int idx = tid + i * 256;
            int r = idx >> 4;
            int q = idx & 15;
            float4 kv = *(const float4*)(Kg + (size_t)(j * 64 + r) * DH + q * 4);
            Kt[(q * 4 + 0) * AST + r] = kv.x;
            Kt[(q * 4 + 1) * AST + r] = kv.y;
            Kt[(q * 4 + 2) * AST + r] = kv.z;
            Kt[(q * 4 + 3) * AST + r] = kv.w;
            float4 vv = *(const float4*)(Vg + (size_t)(j * 64 + r) * DH + q * 4);
            *(float4*)&Vs[r * AST + q * 4] = vv;
        }
        __syncthreads();

        // S = Q * K^T (Q pre-scaled by 1/sqrt(d))
        float s[4][4] = {};
#pragma unroll 16
        for (int d = 0; d < 64; d++) {
            float4 qa = *(const float4*)&Qt[d * AST + r0];
            float4 kb = *(const float4*)&Kt[d * AST + c0];
            float a[4] = {qa.x, qa.y, qa.z, qa.w};
            float b[4] = {kb.x, kb.y, kb.z, kb.w};
#pragma unroll
            for (int ii = 0; ii < 4; ii++)
#pragma unroll
                for (int jj = 0; jj < 4; jj++)
                    s[ii][jj] = fmaf(a[ii], b[jj], s[ii][jj]);
        }

        // Causal mask (only the diagonal tile is partial)
        if (j == iq) {
#pragma unroll
            for (int ii = 0; ii < 4; ii++)
#pragma unroll
                for (int jj = 0; jj < 4; jj++)
                    if (c0 + jj > r0 + ii) s[ii][jj] = -INFINITY;
        }

        // Online softmax update (per-row; reduce across the 16 tx threads)
#pragma unroll
        for (int ii = 0; ii < 4; ii++) {
            float mx = fmaxf(fmaxf(s[ii][0], s[ii][1]), fmaxf(s[ii][2], s[ii][3]));
#pragma unroll
            for (int off = 8; off > 0; off >>= 1)
                mx = fmaxf(mx, __shfl_xor_sync(0xffffffffu, mx, off));
            float mnew = fmaxf(mi[ii], mx);
            float alpha = __expf(mi[ii] - mnew);   // exp(-inf) = 0 on first tile
            float rs = 0.f;
#pragma unroll
            for (int jj = 0; jj < 4; jj++) {
                float p = __expf(s[ii][jj] - mnew);
                s[ii][jj] = p;
                rs += p;
            }
#pragma unroll
            for (int off = 8; off > 0; off >>= 1)
                rs += __shfl_xor_sync(0xffffffffu, rs, off);
            li[ii] = li[ii] * alpha + rs;
            mi[ii] = mnew;
#pragma unroll
            for (int jj = 0; jj < 4; jj++) o[ii][jj] *= alpha;
            *(float4*)&Ps[(r0 + ii) * AST + c0] =
                make_float4(s[ii][0], s[ii][1], s[ii][2], s[ii][3]);
        }
        __syncthreads();

        // O += P * V
#pragma unroll 16
        for (int k = 0; k < 64; k++) {
            float4 vb = *(const float4*)&Vs[k * AST + c0];
            float b[4] = {vb.x, vb.y, vb.z, vb.w};
#pragma unroll
            for (int ii = 0; ii < 4; ii++) {
                float p = Ps[(r0 + ii) * AST + k];
#pragma unroll
                for (int jj = 0; jj < 4; jj++)
                    o[ii][jj] = fmaf(p, b[jj], o[ii][jj]);
            }
        }
    }

    // Normalize and store in [b*T+t][h*64+d] layout
    const int bb = bh >> 4;
    const int hh = bh & 15;
#pragma unroll
    for (int ii = 0; ii < 4; ii++) {
        float inv = 1.f / li[ii];
        float4 vout = make_float4(o[ii][0] * inv, o[ii][1] * inv,
                                  o[ii][2] * inv, o[ii][3] * inv);
        size_t row = (size_t)bb * TSEQ + (size_t)iq * 64 + r0 + ii;
        *(float4*)&g_Oh[row * CDIM + hh * DH + c0] = vout;
    }
}

// ---------------------------------------------------------------------------
// Launch
// ---------------------------------------------------------------------------
extern "C" void kernel_launch(void* const* d_in, const int* in_sizes, int n_in,
                              void* d_out, int out_size)
{
    // Positional defaults (x, mask, Wqkv, Wout) with size-based remap for safety.
    const float* x    = (const float*)d_in[0];
    const float* Wqkv = (const float*)d_in[2];
    const float* Wout = (const float*)d_in[3];
    for (int i = 0; i < n_in; i++) {
        if (in_sizes[i] == BT * CDIM)        x    = (const float*)d_in[i];
        else if (in_sizes[i] == 3 * CDIM * CDIM) Wqkv = (const float*)d_in[i];
        else if (in_sizes[i] == CDIM * CDIM) Wout = (const float*)d_in[i];
        // mask (T*T ints) implemented implicitly as causal
    }
    float* out = (float*)d_out;

    void *p_qkv, *p_oh;
    cudaGetSymbolAddress(&p_qkv, g_qkv);
    cudaGetSymbolAddress(&p_oh, g_Oh);

    const int smem_attn = 4 * 64 * AST * (int)sizeof(float);   // 69632 B
    cudaFuncSetAttribute(attn_kernel,
                         cudaFuncAttributeMaxDynamicSharedMemorySize, smem_attn);

    // 1. RoPE tables (cheap, deterministic)
    build_tables_kernel<<<(TSEQ * 32 + 255) / 256, 256>>>();

    // 2. QKV = x @ Wqkv^T   [8192 x 3072]
    gemm_nt_kernel<<<dim3(3 * CDIM / 128, BT / 128), 256>>>(
        x, Wqkv, (float*)p_qkv, BT, 3 * CDIM, CDIM);

    // 3. RoPE + split into [bh][t][d]
    rope_split_kernel<<<BT, 256>>>();

    // 4. Flash attention (causal)
    attn_kernel<<<dim3(TSEQ / 64, BH), 256, smem_attn>>>();

    // 5. out = attn_out @ Wout^T   [8192 x 1024]
    gemm_nt_kernel<<<dim3(CDIM / 128, BT / 128), 256>>>(
        (const float*)p_oh, Wout, out, BT, CDIM, CDIM);
}

// round 4
// speedup vs baseline: 1.7667x; 1.7667x over previous
#include <cuda_runtime.h>
#include <math.h>
#include <stdint.h>

// Problem constants (fixed by the dataset)
#define BATCH 4
#define TSEQ  2048
#define CDIM  1024
#define NH    16
#define DH    64
#define BT    (BATCH * TSEQ)   // 8192 rows
#define BH    (BATCH * NH)     // 64 (batch*heads)

// ---------------------------------------------------------------------------
// Scratch (device globals; no allocation allowed in kernel_launch)
// ---------------------------------------------------------------------------
__device__ float g_qkv[(size_t)BT * 3 * CDIM];       // 96 MB   x @ Wqkv^T
__device__ float g_Qh[(size_t)BH * TSEQ * DH];       // 32 MB   [bh][t][d], rope'd, *0.125
__device__ float g_Kh[(size_t)BH * TSEQ * DH];       // 32 MB   [bh][t][d], rope'd
__device__ float g_Vh[(size_t)BH * TSEQ * DH];       // 32 MB   [bh][t][d]
__device__ float g_Oh[(size_t)BT * CDIM];            // 32 MB   attention out, [b*T+t][h*64+d]
__device__ float g_cosT[TSEQ * (DH / 2)];            // rope tables
__device__ float g_sinT[TSEQ * (DH / 2)];

// ---------------------------------------------------------------------------
// Helpers
// ---------------------------------------------------------------------------
__device__ __forceinline__ uint32_t tf32u(float x) {
    uint32_t u;
    asm("cvt.rna.tf32.f32 %0, %1;" : "=r"(u) : "f"(x));
    return u;
}

#define MMA_TF32(d, a0, a1, a2, a3, b0, b1)                                  \
    asm volatile(                                                            \
        "mma.sync.aligned.m16n8k8.row.col.f32.tf32.tf32.f32 "                \
        "{%0,%1,%2,%3}, {%4,%5,%6,%7}, {%8,%9}, {%0,%1,%2,%3};"              \
        : "+f"(d[0]), "+f"(d[1]), "+f"(d[2]), "+f"(d[3])                     \
        : "r"(a0), "r"(a1), "r"(a2), "r"(a3), "r"(b0), "r"(b1))

// k-permutation within each 8-wide k-step: element k -> (k>>3)*8 + (k&3)*2 + ((k>>2)&1)
// Makes the (k, k+4) fragment pair adjacent -> one LDS.64 per mma operand pair.
__device__ __forceinline__ int kperm(int k) {
    return ((k >> 3) << 3) + ((k & 3) << 1) + ((k >> 2) & 1);
}

// ---------------------------------------------------------------------------
// RoPE tables (match JAX fp32 semantics: theta fp32, angle fp32 product,
// then exact cos/sin of the rounded angle)
// ---------------------------------------------------------------------------
__global__ void build_tables_kernel() {
    int idx = blockIdx.x * blockDim.x + threadIdx.x;     // t*32 + i
    if (idx >= TSEQ * (DH / 2)) return;
    int t = idx >> 5;
    int i = idx & 31;
    float theta_f = (float)pow(10000.0, -(double)(2 * i) / (double)DH);
    float angle_f = (float)t * theta_f;
    g_cosT[idx] = (float)cos((double)angle_f);
    g_sinT[idx] = (float)sin((double)angle_f);
}

// ---------------------------------------------------------------------------
// NT GEMM via tf32 mma.sync: C[M,N] = A[M,K] * B[N,K]^T, row-major.
// 128x128 block tile, BK=16, 256 threads = 8 warps (2x4 warp grid),
// warp tile 64x32 = 4x4 grid of m16n8k8 mma.
// M%128==0, N%128==0, K%16==0 for every call here.
// ---------------------------------------------------------------------------
#define GP 20   // smem row stride (uints): 16 k's + pad for conflict-free frags

__global__ __launch_bounds__(256) void gemm_nt_tf32(
    const float* __restrict__ A, const float* __restrict__ B,
    float* __restrict__ C, int M, int N, int K)
{
    __shared__ __align__(16) uint32_t As[128 * GP];
    __shared__ __align__(16) uint32_t Bs[128 * GP];

    const int tid  = threadIdx.x;
    const int lane = tid & 31;
    const int w    = tid >> 5;
    const int lr   = lane >> 2;   // group id (0..7)
    const int lc   = lane & 3;    // thread-in-group
    const int wm   = (w >> 2) * 64;
    const int wn   = (w & 3) * 32;
    const int bm   = blockIdx.y * 128;
    const int bn   = blockIdx.x * 128;

    const float* Ab = A + (size_t)bm * K;
    const float* Bb = B + (size_t)bn * K;

    // gmem staging slots: 512 float4 slots for A (and B), 2 per thread
    const int s0 = tid, s1 = tid + 256;
    const int am0 = s0 >> 2, aq0 = s0 & 3;
    const int am1 = s1 >> 2, aq1 = s1 & 3;

    float acc[4][4][4] = {};
    float4 ra0, ra1, rb0, rb1;

    // prologue load (k0 = 0)
    ra0 = *(const float4*)(Ab + (size_t)am0 * K + aq0 * 4);
    ra1 = *(const float4*)(Ab + (size_t)am1 * K + aq1 * 4);
    rb0 = *(const float4*)(Bb + (size_t)am0 * K + aq0 * 4);
    rb1 = *(const float4*)(Bb + (size_t)am1 * K + aq1 * 4);

    const int NIT = K / 16;
    for (int it = 0; it < NIT; it++) {
        // store staged regs to smem (tf32-rounded, k-permuted)
        {
            float va[4] = {ra0.x, ra0.y, ra0.z, ra0.w};
            float vb[4] = {rb0.x, rb0.y, rb0.z, rb0.w};
#pragma unroll
            for (int e = 0; e < 4; e++) {
                int off = kperm(aq0 * 4 + e);
                As[am0 * GP + off] = tf32u(va[e]);
                Bs[am0 * GP + off] = tf32u(vb[e]);
            }
            float vc[4] = {ra1.x, ra1.y, ra1.z, ra1.w};
            float vd[4] = {rb1.x, rb1.y, rb1.z, rb1.w};
#pragma unroll
            for (int e = 0; e < 4; e++) {
                int off = kperm(aq1 * 4 + e);
                As[am1 * GP + off] = tf32u(vc[e]);
                Bs[am1 * GP + off] = tf32u(vd[e]);
            }
        }
        __syncthreads();

        if (it + 1 < NIT) {
            int k0 = (it + 1) * 16;
            ra0 = *(const float4*)(Ab + (size_t)am0 * K + k0 + aq0 * 4);
            ra1 = *(const float4*)(Ab + (size_t)am1 * K + k0 + aq1 * 4);
            rb0 = *(const float4*)(Bb + (size_t)am0 * K + k0 + aq0 * 4);
            rb1 = *(const float4*)(Bb + (size_t)am1 * K + k0 + aq1 * 4);
        }

#pragma unroll
        for (int kk = 0; kk < 2; kk++) {
            uint32_t a[4][4];
#pragma unroll
            for (int mt = 0; mt < 4; mt++) {
                int m = wm + mt * 16 + lr;
                uint2 p0 = *(const uint2*)&As[m * GP + kk * 8 + lc * 2];
                uint2 p1 = *(const uint2*)&As[(m + 8) * GP + kk * 8 + lc * 2];
                a[mt][0] = p0.x; a[mt][2] = p0.y;   // (g,k), (g,k+4)
                a[mt][1] = p1.x; a[mt][3] = p1.y;   // (g+8,k), (g+8,k+4)
            }
            uint32_t b[4][2];
#pragma unroll
            for (int nt = 0; nt < 4; nt++) {
                int n = wn + nt * 8 + lr;
                uint2 q = *(const uint2*)&Bs[n * GP + kk * 8 + lc * 2];
                b[nt][0] = q.x; b[nt][1] = q.y;
            }
#pragma unroll
            for (int mt = 0; mt < 4; mt++)
#pragma unroll
                for (int nt = 0; nt < 4; nt++)
                    MMA_TF32(acc[mt][nt], a[mt][0], a[mt][1], a[mt][2], a[mt][3],
                             b[nt][0], b[nt][1]);
        }
        __syncthreads();
    }

    // epilogue
#pragma unroll
    for (int mt = 0; mt < 4; mt++) {
#pragma unroll
        for (int nt = 0; nt < 4; nt++) {
            size_t r = (size_t)(bm + wm + mt * 16 + lr);
            int col = bn + wn + nt * 8 + 2 * lc;
            *(float2*)&C[r * N + col] =
                make_float2(acc[mt][nt][0], acc[mt][nt][1]);
            *(float2*)&C[(r + 8) * N + col] =
                make_float2(acc[mt][nt][2], acc[mt][nt][3]);
        }
    }
}

// ---------------------------------------------------------------------------
// RoPE + head split
// ---------------------------------------------------------------------------
__global__ __launch_bounds__(256) void rope_split_kernel() {
    const int row = blockIdx.x;                  // b*T + t
    const int b = row >> 11;
    const int t = row & (TSEQ - 1);
    const float* src = g_qkv + (size_t)row * (3 * CDIM);

    for (int p = threadIdx.x; p < 3 * CDIM / 2; p += blockDim.x) {
        int col = p * 2;
        int s = col >> 10;                       // 0=q 1=k 2=v
        int within = col & (CDIM - 1);
        int h = within >> 6;
        int j = within & (DH - 1);               // even
        float2 xv = *(const float2*)(src + col);
        size_t dst = (((size_t)(b * NH + h) * TSEQ) + t) * DH + j;
        if (s == 2) {
            *(float2*)(g_Vh + dst) = xv;
        } else {
            float c = g_cosT[t * 32 + (j >> 1)];
            float sn = g_sinT[t * 32 + (j >> 1)];
            float o0 = xv.x * c - xv.y * sn;
            float o1 = xv.y * c + xv.x * sn;
            if (s == 0) {
                o0 *= 0.125f; o1 *= 0.125f;      // 1/sqrt(d_head) folded into Q
                *(float2*)(g_Qh + dst) = make_float2(o0, o1);
            } else {
                *(float2*)(g_Kh + dst) = make_float2(o0, o1);
            }
        }
    }
}

// ---------------------------------------------------------------------------
// Flash attention with tf32 mma. 64 q-rows per CTA (4 warps x m16), 64-key
// tiles, online softmax on C fragments. P staged via smem (tf32), V staged
// transposed+key-permuted so it serves as the B operand of O += P*V.
// ---------------------------------------------------------------------------
#define AP 68   // smem row stride (uints)

__global__ __launch_bounds__(128) void attn_tc_kernel() {
    extern __shared__ uint32_t sm[];
    uint32_t* Qs = sm;              // [64 q][AP]    d-permuted
    uint32_t* Ks = Qs + 64 * AP;    // [64 key][AP]  d-permuted
    uint32_t* Vt = Ks + 64 * AP;    // [64 d][AP]    key-permuted (transposed)
    uint32_t* Ps = Vt + 64 * AP;    // [64 q][AP]    key-permuted

    const int tid  = threadIdx.x;
    const int lane = tid & 31;
    const int w    = tid >> 5;      // warp 0..3 -> q rows w*16..w*16+15
    const int lr   = lane >> 2;
    const int lc   = lane & 3;
    const int iq   = blockIdx.x;    // q tile (64 rows)
    const int bh   = blockIdx.y;

    const float* Qg = g_Qh + ((size_t)bh * TSEQ + iq * 64) * DH;
    const float* Kg = g_Kh + (size_t)bh * TSEQ * DH;
    const float* Vg = g_Vh + (size_t)bh * TSEQ * DH;

    // Load Q tile: 64x64, 1024 float4 slots / 128 threads = 8 each
#pragma unroll
    for (int i = 0; i < 8; i++) {
        int slot = tid + i * 128;
        int r = slot >> 4;
        int qq = slot & 15;
        float4 v = *(const float4*)(Qg + r * DH + qq * 4);
        float vv[4] = {v.x, v.y, v.z, v.w};
#pragma unroll
        for (int e = 0; e < 4; e++)
            Qs[r * AP + kperm(qq * 4 + e)] = tf32u(vv[e]);
    }

    float oacc[8][4] = {};
    float mrow[2] = {-INFINITY, -INFINITY};
    float lrow[2] = {0.f, 0.f};

    for (int j = 0; j <= iq; j++) {
        __syncthreads();   // prior PV reads of Ks/Vt done; Q store done (j==0)
#pragma unroll
        for (int i = 0; i < 8; i++) {
            int slot = tid + i * 128;
            int r = slot >> 4;
            int qq = slot & 15;
            float4 kv = *(const float4*)(Kg + (size_t)(j * 64 + r) * DH + qq * 4);
            float ka[4] = {kv.x, kv.y, kv.z, kv.w};
#pragma unroll
            for (int e = 0; e < 4; e++)
                Ks[r * AP + kperm(qq * 4 + e)] = tf32u(ka[e]);
            float4 vv = *(const float4*)(Vg + (size_t)(j * 64 + r) * DH + qq * 4);
            float va[4] = {vv.x, vv.y, vv.z, vv.w};
            int kp = kperm(r);
#pragma unroll
            for (int e = 0; e < 4; e++)
                Vt[(qq * 4 + e) * AP + kp] = tf32u(va[e]);
        }
        __syncthreads();

        // S = Q * K^T   (warp-local m16 x n64, k=64)
        float s[8][4] = {};
#pragma unroll
        for (int kk = 0; kk < 8; kk++) {
            int m = w * 16 + lr;
            uint2 p0 = *(const uint2*)&Qs[m * AP + kk * 8 + lc * 2];
            uint2 p1 = *(const uint2*)&Qs[(m + 8) * AP + kk * 8 + lc * 2];
            uint32_t a0 = p0.x, a2 = p0.y, a1 = p1.x, a3 = p1.y;
#pragma unroll
            for (int nt = 0; nt < 8; nt++) {
                uint2 q = *(const uint2*)&Ks[(nt * 8 + lr) * AP + kk * 8 + lc * 2];
                MMA_TF32(s[nt], a0, a1, a2, a3, q.x, q.y);
            }
        }

        // causal mask on the diagonal tile
        if (j == iq) {
#pragma unroll
            for (int nt = 0; nt < 8; nt++) {
#pragma unroll
                for (int e = 0; e < 4; e++) {
                    int rl = w * 16 + lr + (e >> 1) * 8;
                    int cl = nt * 8 + 2 * lc + (e & 1);
                    if (cl > rl) s[nt][e] = -INFINITY;
                }
            }
        }

        // online softmax per row half (h=0: rows lr; h=1: rows lr+8)
#pragma unroll
        for (int h = 0; h < 2; h++) {
            float mx = -INFINITY;
#pragma unroll
            for (int nt = 0; nt < 8; nt++)
                mx = fmaxf(mx, fmaxf(s[nt][2 * h], s[nt][2 * h + 1]));
            mx = fmaxf(mx, __shfl_xor_sync(0xffffffffu, mx, 1));
            mx = fmaxf(mx, __shfl_xor_sync(0xffffffffu, mx, 2));
            float mnew = fmaxf(mrow[h], mx);
            float alpha = __expf(mrow[h] - mnew);
            float rs = 0.f;
#pragma unroll
            for (int nt = 0; nt < 8; nt++) {
                float p0 = __expf(s[nt][2 * h] - mnew);
                float p1 = __expf(s[nt][2 * h + 1] - mnew);
                s[nt][2 * h] = p0;
                s[nt][2 * h + 1] = p1;
                rs += p0 + p1;
            }
            rs += __shfl_xor_sync(0xffffffffu, rs, 1);
            rs += __shfl_xor_sync(0xffffffffu, rs, 2);
            lrow[h] = lrow[h] * alpha + rs;
            mrow[h] = mnew;
#pragma unroll
            for (int nt = 0; nt < 8; nt++) {
                oacc[nt][2 * h] *= alpha;
                oacc[nt][2 * h + 1] *= alpha;
            }
            // store P (tf32-rounded, key-permuted) for the PV mma
            int pr = w * 16 + lr + 8 * h;
#pragma unroll
            for (int nt = 0; nt < 8; nt++) {
                int c0 = nt * 8 + 2 * lc;
                Ps[pr * AP + kperm(c0)]     = tf32u(s[nt][2 * h]);
                Ps[pr * AP + kperm(c0 + 1)] = tf32u(s[nt][2 * h + 1]);
            }
        }
        __syncwarp();   // Ps rows for this warp are warp-private

        // O += P * V   (warp-local m16 x n64, k=64 keys)
#pragma unroll
        for (int kk = 0; kk < 8; kk++) {
            int m = w * 16 + lr;
            uint2 p0 = *(const uint2*)&Ps[m * AP + kk * 8 + lc * 2];
            uint2 p1 = *(const uint2*)&Ps[(m + 8) * AP + kk * 8 + lc * 2];
            uint32_t a0 = p0.x, a2 = p0.y, a1 = p1.x, a3 = p1.y;
#pragma unroll
            for (int nt = 0; nt < 8; nt++) {
                uint2 q = *(const uint2*)&Vt[(nt * 8 + lr) * AP + kk * 8 + lc * 2];
                MMA_TF32(oacc[nt], a0, a1, a2, a3, q.x, q.y);
            }
        }
    }

    // epilogue: normalize and write to [b*T+t][h*64+d]
    const int bb = bh >> 4;
    const int hh = bh & 15;
#pragma unroll
    for (int h = 0; h < 2; h++) {
        float inv = 1.f / lrow[h];
        size_t row = (size_t)bb * TSEQ + (size_t)iq * 64 + w * 16 + lr + 8 * h;
        float* dst = g_Oh + row * CDIM + hh * DH;
#pragma unroll
        for (int nt = 0; nt < 8; nt++) {
            int col = nt * 8 + 2 * lc;
            *(float2*)&dst[col] = make_float2(oacc[nt][2 * h] * inv,
                                              oacc[nt][2 * h + 1] * inv);
        }
    }
}

// ---------------------------------------------------------------------------
// Launch
// ---------------------------------------------------------------------------
extern "C" void kernel_launch(void* const* d_in, const int* in_sizes, int n_in,
                              void* d_out, int out_size)
{
    const float* x    = (const float*)d_in[0];
    const float* Wqkv = (const float*)d_in[2];
    const float* Wout = (const float*)d_in[3];
    for (int i = 0; i < n_in; i++) {
        if (in_sizes[i] == BT * CDIM)            x    = (const float*)d_in[i];
        else if (in_sizes[i] == 3 * CDIM * CDIM) Wqkv = (const float*)d_in[i];
        else if (in_sizes[i] == CDIM * CDIM)     Wout = (const float*)d_in[i];
    }
    float* out = (float*)d_out;

    void *p_qkv, *p_oh;
    cudaGetSymbolAddress(&p_qkv, g_qkv);
    cudaGetSymbolAddress(&p_oh, g_Oh);

    const int smem_attn = 4 * 64 * AP * (int)sizeof(uint32_t);   // 69632 B
    cudaFuncSetAttribute(attn_tc_kernel,
                         cudaFuncAttributeMaxDynamicSharedMemorySize, smem_attn);

    // 1. RoPE tables
    build_tables_kernel<<<(TSEQ * 32 + 255) / 256, 256>>>();

    // 2. QKV = x @ Wqkv^T   [8192 x 3072]
    gemm_nt_tf32<<<dim3(3 * CDIM / 128, BT / 128), 256>>>(
        x, Wqkv, (float*)p_qkv, BT, 3 * CDIM, CDIM);

    // 3. RoPE + split into [bh][t][d]
    rope_split_kernel<<<BT, 256>>>();

    // 4. Flash attention (causal, tf32 tensor cores)
    attn_tc_kernel<<<dim3(TSEQ / 64, BH), 128, smem_attn>>>();

    // 5. out = attn_out @ Wout^T   [8192 x 1024]
    gemm_nt_tf32<<<dim3(CDIM / 128, BT / 128), 256>>>(
        (const float*)p_oh, Wout, out, BT, CDIM, CDIM);
}

// round 7
// speedup vs baseline: 2.2748x; 1.2876x over previous
#include <cuda_runtime.h>
#include <math.h>
#include <stdint.h>

// Problem constants (fixed by the dataset)
#define BATCH 4
#define TSEQ  2048
#define CDIM  1024
#define NH    16
#define DH    64
#define BT    (BATCH * TSEQ)   // 8192 rows
#define BH    (BATCH * NH)     // 64 (batch*heads)

// ---------------------------------------------------------------------------
// Scratch (device globals; no allocation allowed in kernel_launch)
// ---------------------------------------------------------------------------
__device__ float g_qkv[(size_t)BT * 3 * CDIM];       // 96 MB   x @ Wqkv^T
__device__ float g_Qh[(size_t)BH * TSEQ * DH];       // 32 MB   [bh][t][d], rope'd, *0.125
__device__ float g_Kh[(size_t)BH * TSEQ * DH];       // 32 MB   [bh][t][d], rope'd
__device__ float g_Vh[(size_t)BH * TSEQ * DH];       // 32 MB   [bh][t][d]
__device__ float g_Oh[(size_t)BT * CDIM];            // 32 MB   attention out, [b*T+t][h*64+d]
__device__ float g_cosT[TSEQ * (DH / 2)];            // rope tables
__device__ float g_sinT[TSEQ * (DH / 2)];

// ---------------------------------------------------------------------------
// Helpers
// ---------------------------------------------------------------------------
__device__ __forceinline__ uint32_t tf32u(float x) {
    uint32_t u;
    asm("cvt.rna.tf32.f32 %0, %1;" : "=r"(u) : "f"(x));
    return u;
}

#define MMA_TF32(d, a0, a1, a2, a3, b0, b1)                                  \
    asm volatile(                                                            \
        "mma.sync.aligned.m16n8k8.row.col.f32.tf32.tf32.f32 "                \
        "{%0,%1,%2,%3}, {%4,%5,%6,%7}, {%8,%9}, {%0,%1,%2,%3};"              \
        : "+f"(d[0]), "+f"(d[1]), "+f"(d[2]), "+f"(d[3])                     \
        : "r"(a0), "r"(a1), "r"(a2), "r"(a3), "r"(b0), "r"(b1))

// k-permutation within each 8-wide k-step: k -> (k>>3)*8 + (k&3)*2 + ((k>>2)&1)
// (k, k+4) fragment pairs become adjacent -> LDS.64 per mma B operand.
__device__ __forceinline__ int kperm(int k) {
    return ((k >> 3) << 3) + ((k & 3) << 1) + ((k >> 2) & 1);
}

// ---------------------------------------------------------------------------
// RoPE tables
// ---------------------------------------------------------------------------
__global__ void build_tables_kernel() {
    int idx = blockIdx.x * blockDim.x + threadIdx.x;     // t*32 + i
    if (idx >= TSEQ * (DH / 2)) return;
    int t = idx >> 5;
    int i = idx & 31;
    float theta_f = (float)pow(10000.0, -(double)(2 * i) / (double)DH);
    float angle_f = (float)t * theta_f;
    g_cosT[idx] = (float)cos((double)angle_f);
    g_sinT[idx] = (float)sin((double)angle_f);
}

// ---------------------------------------------------------------------------
// NT GEMM via tf32 mma.sync: C[M,N] = A[M,K] * B[N,K]^T, row-major.
// 128x128 block tile, BK=16, 256 threads = 8 warps, warp tile 64x32.
// Staging: paired LDG.64 -> single STS.128 into the kperm'd layout.
// ---------------------------------------------------------------------------
#define GP 20   // smem row stride (uints)

__global__ __launch_bounds__(256) void gemm_nt_tf32(
    const float* __restrict__ A, const float* __restrict__ B,
    float* __restrict__ C, int M, int N, int K)
{
    __shared__ __align__(16) uint32_t As[128 * GP];
    __shared__ __align__(16) uint32_t Bs[128 * GP];

    const int tid  = threadIdx.x;
    const int lane = tid & 31;
    const int w    = tid >> 5;
    const int lr   = lane >> 2;
    const int lc   = lane & 3;
    const int wm   = (w >> 2) * 64;
    const int wn   = (w & 3) * 32;
    const int bm   = blockIdx.y * 128;
    const int bn   = blockIdx.x * 128;

    const float* Ab = A + (size_t)bm * K;
    const float* Bb = B + (size_t)bn * K;

    // staging chunks: 128 rows x 4 chunks (each chunk = 8-k block half-pair)
    const int s0 = tid, s1 = tid + 256;            // 512 chunks per matrix
    const int m0 = s0 >> 2, c0_ = s0 & 3;
    const int m1 = s1 >> 2, c1_ = s1 & 3;
    const int b0_ = (c0_ >> 1) << 3, h0 = c0_ & 1;
    const int b1_ = (c1_ >> 1) << 3, h1 = c1_ & 1;

    float acc[4][4][4] = {};
    float2 a0u, a0v, a1u, a1v, b0u, b0v, b1u, b1v;

    // prologue (k0 = 0)
    a0u = *(const float2*)(Ab + (size_t)m0 * K + b0_ + 2 * h0);
    a0v = *(const float2*)(Ab + (size_t)m0 * K + b0_ + 2 * h0 + 4);
    a1u = *(const float2*)(Ab + (size_t)m1 * K + b1_ + 2 * h1);
    a1v = *(const float2*)(Ab + (size_t)m1 * K + b1_ + 2 * h1 + 4);
    b0u = *(const float2*)(Bb + (size_t)m0 * K + b0_ + 2 * h0);
    b0v = *(const float2*)(Bb + (size_t)m0 * K + b0_ + 2 * h0 + 4);
    b1u = *(const float2*)(Bb + (size_t)m1 * K + b1_ + 2 * h1);
    b1v = *(const float2*)(Bb + (size_t)m1 * K + b1_ + 2 * h1 + 4);

    const int NIT = K / 16;
    for (int it = 0; it < NIT; it++) {
        // kperm'd vector stores: block [b + 4h .. b + 4h + 3] = (u.x, v.x, u.y, v.y)
        *(uint4*)&As[m0 * GP + b0_ + 4 * h0] =
            make_uint4(tf32u(a0u.x), tf32u(a0v.x), tf32u(a0u.y), tf32u(a0v.y));
        *(uint4*)&As[m1 * GP + b1_ + 4 * h1] =
            make_uint4(tf32u(a1u.x), tf32u(a1v.x), tf32u(a1u.y), tf32u(a1v.y));
        *(uint4*)&Bs[m0 * GP + b0_ + 4 * h0] =
            make_uint4(tf32u(b0u.x), tf32u(b0v.x), tf32u(b0u.y), tf32u(b0v.y));
        *(uint4*)&Bs[m1 * GP + b1_ + 4 * h1] =
            make_uint4(tf32u(b1u.x), tf32u(b1v.x), tf32u(b1u.y), tf32u(b1v.y));
        __syncthreads();

        if (it + 1 < NIT) {
            int k0 = (it + 1) * 16;
            a0u = *(const float2*)(Ab + (size_t)m0 * K + k0 + b0_ + 2 * h0);
            a0v = *(const float2*)(Ab + (size_t)m0 * K + k0 + b0_ + 2 * h0 + 4);
            a1u = *(const float2*)(Ab + (size_t)m1 * K + k0 + b1_ + 2 * h1);
            a1v = *(const float2*)(Ab + (size_t)m1 * K + k0 + b1_ + 2 * h1 + 4);
            b0u = *(const float2*)(Bb + (size_t)m0 * K + k0 + b0_ + 2 * h0);
            b0v = *(const float2*)(Bb + (size_t)m0 * K + k0 + b0_ + 2 * h0 + 4);
            b1u = *(const float2*)(Bb + (size_t)m1 * K + k0 + b1_ + 2 * h1);
            b1v = *(const float2*)(Bb + (size_t)m1 * K + k0 + b1_ + 2 * h1 + 4);
        }

#pragma unroll
        for (int kk = 0; kk < 2; kk++) {
            uint32_t a[4][4];
#pragma unroll
            for (int mt = 0; mt < 4; mt++) {
                int m = wm + mt * 16 + lr;
                uint2 p0 = *(const uint2*)&As[m * GP + kk * 8 + lc * 2];
                uint2 p1 = *(const uint2*)&As[(m + 8) * GP + kk * 8 + lc * 2];
                a[mt][0] = p0.x; a[mt][2] = p0.y;
                a[mt][1] = p1.x; a[mt][3] = p1.y;
            }
            uint32_t b[4][2];
#pragma unroll
            for (int nt = 0; nt < 4; nt++) {
                int n = wn + nt * 8 + lr;
                uint2 q = *(const uint2*)&Bs[n * GP + kk * 8 + lc * 2];
                b[nt][0] = q.x; b[nt][1] = q.y;
            }
#pragma unroll
            for (int mt = 0; mt < 4; mt++)
#pragma unroll
                for (int nt = 0; nt < 4; nt++)
                    MMA_TF32(acc[mt][nt], a[mt][0], a[mt][1], a[mt][2], a[mt][3],
                             b[nt][0], b[nt][1]);
        }
        __syncthreads();
    }

#pragma unroll
    for (int mt = 0; mt < 4; mt++) {
#pragma unroll
        for (int nt = 0; nt < 4; nt++) {
            size_t r = (size_t)(bm + wm + mt * 16 + lr);
            int col = bn + wn + nt * 8 + 2 * lc;
            *(float2*)&C[r * N + col] =
                make_float2(acc[mt][nt][0], acc[mt][nt][1]);
            *(float2*)&C[(r + 8) * N + col] =
                make_float2(acc[mt][nt][2], acc[mt][nt][3]);
        }
    }
}

// ---------------------------------------------------------------------------
// RoPE + head split
// ---------------------------------------------------------------------------
__global__ __launch_bounds__(256) void rope_split_kernel() {
    const int row = blockIdx.x;                  // b*T + t
    const int b = row >> 11;
    const int t = row & (TSEQ - 1);
    const float* src = g_qkv + (size_t)row * (3 * CDIM);

    for (int p = threadIdx.x; p < 3 * CDIM / 2; p += blockDim.x) {
        int col = p * 2;
        int s = col >> 10;                       // 0=q 1=k 2=v
        int within = col & (CDIM - 1);
        int h = within >> 6;
        int j = within & (DH - 1);               // even
        float2 xv = *(const float2*)(src + col);
        size_t dst = (((size_t)(b * NH + h) * TSEQ) + t) * DH + j;
        if (s == 2) {
            *(float2*)(g_Vh + dst) = xv;
        } else {
            float c = g_cosT[t * 32 + (j >> 1)];
            float sn = g_sinT[t * 32 + (j >> 1)];
            float o0 = xv.x * c - xv.y * sn;
            float o1 = xv.y * c + xv.x * sn;
            if (s == 0) {
                o0 *= 0.125f; o1 *= 0.125f;      // 1/sqrt(d_head) folded into Q
                *(float2*)(g_Qh + dst) = make_float2(o0, o1);
            } else {
                *(float2*)(g_Kh + dst) = make_float2(o0, o1);
            }
        }
    }
}

// ---------------------------------------------------------------------------
// Flash attention, tf32 mma. Q tile = 128 rows (8 warps x m16), K tile = 64.
// Q fragments live in registers for the whole kernel. K stored kperm'd
// (LDS.64 B-frags), V stored natural (2x conflict-free LDS.32 B-frags),
// P stored natural (STS.64 / LDS.32). All staging stores are STS.128.
// ---------------------------------------------------------------------------
#define APK 72   // K smem row stride (72 % 32 == 8 -> conflict-free LDS.64)
#define APV 72   // V smem row stride
#define APP 76   // P smem row stride (76 % 32 == 12 -> conflict-free LDS.32)

__global__ __launch_bounds__(256) void attn_tc_kernel() {
    extern __shared__ uint32_t sm[];
    uint32_t* Ks = sm;                  // [64 key][APK]   d kperm'd
    uint32_t* Vs = Ks + 64 * APK;       // [64 key][APV]   natural [key][d]
    uint32_t* Ps = Vs + 64 * APV;       // [128 q][APP]    natural [q][key]

    const int tid  = threadIdx.x;
    const int lane = tid & 31;
    const int w    = tid >> 5;          // warp 0..7 -> q rows w*16..w*16+15
    const int lr   = lane >> 2;
    const int lc   = lane & 3;
    const int iq   = blockIdx.x;        // q tile (128 rows)
    const int bh   = blockIdx.y;

    const float* Qg = g_Qh + ((size_t)bh * TSEQ + iq * 128) * DH;
    const float* Kg = g_Kh + (size_t)bh * TSEQ * DH;
    const float* Vg = g_Vh + (size_t)bh * TSEQ * DH;

    // Q fragments -> registers (reused for every key tile)
    uint32_t qf[8][4];
    {
        const float* q0 = Qg + (w * 16 + lr) * DH;
        const float* q1 = q0 + 8 * DH;
#pragma unroll
        for (int kk = 0; kk < 8; kk++) {
            qf[kk][0] = tf32u(q0[kk * 8 + lc]);
            qf[kk][1] = tf32u(q1[kk * 8 + lc]);
            qf[kk][2] = tf32u(q0[kk * 8 + lc + 4]);
            qf[kk][3] = tf32u(q1[kk * 8 + lc + 4]);
        }
    }

    float oacc[8][4] = {};
    float mrow[2] = {-INFINITY, -INFINITY};
    float lrow[2] = {0.f, 0.f};

    const int NJ = 2 * iq + 2;          // key tiles covering keys <= max row
    for (int j = 0; j < NJ; j++) {
        __syncthreads();                // prior tile's Ks/Vs reads complete
        // ---- stage K (kperm, STS.128) and V (natural, STS.128) ----
        const float* Kt = Kg + (size_t)(j * 64) * DH;
        const float* Vt = Vg + (size_t)(j * 64) * DH;
#pragma unroll
        for (int i = 0; i < 4; i++) {
            int chunk = tid + i * 256;           // 0..1023
            int r = chunk >> 4;
            int c = chunk & 15;
            int b = (c >> 1) << 3;
            int h = c & 1;
            const float* src = Kt + r * DH + b + 2 * h;
            float2 u  = *(const float2*)src;
            float2 v2 = *(const float2*)(src + 4);
            // kperm block [b+4h .. b+4h+3] = (k, k+4, k+1, k+5)
            *(uint4*)&Ks[r * APK + b + 4 * h] =
                make_uint4(tf32u(u.x), tf32u(v2.x), tf32u(u.y), tf32u(v2.y));
            float4 vv = *(const float4*)(Vt + r * DH + c * 4);
            *(uint4*)&Vs[r * APV + c * 4] =
                make_uint4(tf32u(vv.x), tf32u(vv.y), tf32u(vv.z), tf32u(vv.w));
        }
        __syncthreads();

        // ---- S = Q K^T  (m16 x n64, k=64) ----
        float s[8][4] = {};
#pragma unroll
        for (int kk = 0; kk < 8; kk++) {
#pragma unroll
            for (int nt = 0; nt < 8; nt++) {
                uint2 b2 = *(const uint2*)&Ks[(nt * 8 + lr) * APK + kk * 8 + 2 * lc];
                MMA_TF32(s[nt], qf[kk][0], qf[kk][1], qf[kk][2], qf[kk][3],
                         b2.x, b2.y);
            }
        }

        // ---- causal mask (only the last two tiles can be partial) ----
        if (j >= 2 * iq) {
            int rbase = iq * 128 + w * 16 + lr;
            int cbase = j * 64 + 2 * lc;
#pragma unroll
            for (int nt = 0; nt < 8; nt++) {
#pragma unroll
                for (int e = 0; e < 4; e++) {
                    int rl = rbase + (e >> 1) * 8;
                    int cl = cbase + nt * 8 + (e & 1);
                    if (cl > rl) s[nt][e] = -INFINITY;
                }
            }
        }

        // ---- online softmax (per row half) + P store ----
#pragma unroll
        for (int h = 0; h < 2; h++) {
            float mx = -INFINITY;
#pragma unroll
            for (int nt = 0; nt < 8; nt++)
                mx = fmaxf(mx, fmaxf(s[nt][2 * h], s[nt][2 * h + 1]));
            mx = fmaxf(mx, __shfl_xor_sync(0xffffffffu, mx, 1));
            mx = fmaxf(mx, __shfl_xor_sync(0xffffffffu, mx, 2));
            float mnew = fmaxf(mrow[h], mx);
            float alpha = __expf(mrow[h] - mnew);
            float rs = 0.f;
#pragma unroll
            for (int nt = 0; nt < 8; nt++) {
                float p0 = __expf(s[nt][2 * h] - mnew);
                float p1 = __expf(s[nt][2 * h + 1] - mnew);
                s[nt][2 * h] = p0;
                s[nt][2 * h + 1] = p1;
                rs += p0 + p1;
            }
            rs += __shfl_xor_sync(0xffffffffu, rs, 1);
            rs += __shfl_xor_sync(0xffffffffu, rs, 2);
            lrow[h] = lrow[h] * alpha + rs;
            mrow[h] = mnew;
#pragma unroll
            for (int nt = 0; nt < 8; nt++) {
                oacc[nt][2 * h] *= alpha;
                oacc[nt][2 * h + 1] *= alpha;
            }
            int pr = w * 16 + lr + 8 * h;
#pragma unroll
            for (int nt = 0; nt < 8; nt++) {
                *(uint2*)&Ps[pr * APP + nt * 8 + 2 * lc] =
                    make_uint2(tf32u(s[nt][2 * h]), tf32u(s[nt][2 * h + 1]));
            }
        }
        __syncwarp();   // this warp's Ps rows only

        // ---- O += P * V  (m16 x n64, k=64 keys) ----
#pragma unroll
        for (int kk = 0; kk < 8; kk++) {
            int m = w * 16 + lr;
            uint32_t a0 = Ps[m * APP + kk * 8 + lc];
            uint32_t a1 = Ps[(m + 8) * APP + kk * 8 + lc];
            uint32_t a2 = Ps[m * APP + kk * 8 + lc + 4];
            uint32_t a3 = Ps[(m + 8) * APP + kk * 8 + lc + 4];
#pragma unroll
            for (int nt = 0; nt < 8; nt++) {
                uint32_t b0 = Vs[(kk * 8 + lc) * APV + nt * 8 + lr];
                uint32_t b1 = Vs[(kk * 8 + lc + 4) * APV + nt * 8 + lr];
                MMA_TF32(oacc[nt], a0, a1, a2, a3, b0, b1);
            }
        }
    }

    // ---- epilogue: normalize, write [b*T+t][h*64+d] ----
    const int bb = bh >> 4;
    const int hh = bh & 15;
#pragma unroll
    for (int h = 0; h < 2; h++) {
        float inv = 1.f / lrow[h];
        size_t row = (size_t)bb * TSEQ + (size_t)iq * 128 + w * 16 + lr + 8 * h;
        float* dst = g_Oh + row * CDIM + hh * DH;
#pragma unroll
        for (int nt = 0; nt < 8; nt++) {
            int col = nt * 8 + 2 * lc;
            *(float2*)&dst[col] = make_float2(oacc[nt][2 * h] * inv,
                                              oacc[nt][2 * h + 1] * inv);
        }
    }
}

// ---------------------------------------------------------------------------
// Launch
// ---------------------------------------------------------------------------
extern "C" void kernel_launch(void* const* d_in, const int* in_sizes, int n_in,
                              void* d_out, int out_size)
{
    const float* x    = (const float*)d_in[0];
    const float* Wqkv = (const float*)d_in[2];
    const float* Wout = (const float*)d_in[3];
    for (int i = 0; i < n_in; i++) {
        if (in_sizes[i] == BT * CDIM)            x    = (const float*)d_in[i];
        else if (in_sizes[i] == 3 * CDIM * CDIM) Wqkv = (const float*)d_in[i];
        else if (in_sizes[i] == CDIM * CDIM)     Wout = (const float*)d_in[i];
    }
    float* out = (float*)d_out;

    void *p_qkv, *p_oh;
    cudaGetSymbolAddress(&p_qkv, g_qkv);
    cudaGetSymbolAddress(&p_oh, g_Oh);

    const int smem_attn = (64 * APK + 64 * APV + 128 * APP) * (int)sizeof(uint32_t);
    cudaFuncSetAttribute(attn_tc_kernel,
                         cudaFuncAttributeMaxDynamicSharedMemorySize, smem_attn);

    // 1. RoPE tables
    build_tables_kernel<<<(TSEQ * 32 + 255) / 256, 256>>>();

    // 2. QKV = x @ Wqkv^T   [8192 x 3072]
    gemm_nt_tf32<<<dim3(3 * CDIM / 128, BT / 128), 256>>>(
        x, Wqkv, (float*)p_qkv, BT, 3 * CDIM, CDIM);

    // 3. RoPE + split into [bh][t][d]
    rope_split_kernel<<<BT, 256>>>();

    // 4. Flash attention (causal, tf32 tensor cores, 128-row Q tiles)
    attn_tc_kernel<<<dim3(TSEQ / 128, BH), 256, smem_attn>>>();

    // 5. out = attn_out @ Wout^T   [8192 x 1024]
    gemm_nt_tf32<<<dim3(CDIM / 128, BT / 128), 256>>>(
        (const float*)p_oh, Wout, out, BT, CDIM, CDIM);
}

// round 9
// speedup vs baseline: 2.4221x; 1.0648x over previous
#include <cuda_runtime.h>
#include <math.h>
#include <stdint.h>

// Problem constants (fixed by the dataset)
#define BATCH 4
#define TSEQ  2048
#define CDIM  1024
#define NH    16
#define DH    64
#define BT    (BATCH * TSEQ)   // 8192 rows
#define BH    (BATCH * NH)     // 64 (batch*heads)

// ---------------------------------------------------------------------------
// Scratch (device globals; no allocation allowed in kernel_launch)
// ---------------------------------------------------------------------------
__device__ float g_qkv[(size_t)BT * 3 * CDIM];       // 96 MB   x @ Wqkv^T
__device__ float g_Qh[(size_t)BH * TSEQ * DH];       // 32 MB   [bh][t][d], rope'd, *0.125
__device__ float g_Kh[(size_t)BH * TSEQ * DH];       // 32 MB   [bh][t][d], rope'd
__device__ float g_Vh[(size_t)BH * TSEQ * DH];       // 32 MB   [bh][t][d]
__device__ float g_Oh[(size_t)BT * CDIM];            // 32 MB   attention out, [b*T+t][h*64+d]
__device__ float g_cosT[TSEQ * (DH / 2)];            // rope tables
__device__ float g_sinT[TSEQ * (DH / 2)];

// ---------------------------------------------------------------------------
// Helpers
// ---------------------------------------------------------------------------
__device__ __forceinline__ uint32_t tf32u(float x) {
    uint32_t u;
    asm("cvt.rna.tf32.f32 %0, %1;" : "=r"(u) : "f"(x));
    return u;
}

#define MMA_TF32(d, a0, a1, a2, a3, b0, b1)                                  \
    asm volatile(                                                            \
        "mma.sync.aligned.m16n8k8.row.col.f32.tf32.tf32.f32 "                \
        "{%0,%1,%2,%3}, {%4,%5,%6,%7}, {%8,%9}, {%0,%1,%2,%3};"              \
        : "+f"(d[0]), "+f"(d[1]), "+f"(d[2]), "+f"(d[3])                     \
        : "r"(a0), "r"(a1), "r"(a2), "r"(a3), "r"(b0), "r"(b1))

// k-permutation within each 8-wide k-step: k -> (k>>3)*8 + (k&3)*2 + ((k>>2)&1)
// (k, k+4) fragment pairs become adjacent -> LDS.64 per mma B operand.
__device__ __forceinline__ int kperm(int k) {
    return ((k >> 3) << 3) + ((k & 3) << 1) + ((k >> 2) & 1);
}

// ---------------------------------------------------------------------------
// RoPE tables
// ---------------------------------------------------------------------------
__global__ void build_tables_kernel() {
    int idx = blockIdx.x * blockDim.x + threadIdx.x;     // t*32 + i
    if (idx >= TSEQ * (DH / 2)) return;
    int t = idx >> 5;
    int i = idx & 31;
    float theta_f = (float)pow(10000.0, -(double)(2 * i) / (double)DH);
    float angle_f = (float)t * theta_f;
    g_cosT[idx] = (float)cos((double)angle_f);
    g_sinT[idx] = (float)sin((double)angle_f);
}

// ---------------------------------------------------------------------------
// NT GEMM via tf32 mma.sync: C[M,N] = A[M,K] * B[N,K]^T, row-major.
// 128x128 block tile, BK=16, 256 threads = 8 warps, warp tile 64x32.
// Double-buffered smem: one __syncthreads per iteration; LDG(it+1) issued
// before the compute of it, STS(it+1) after it -> global latency hidden.
// Staging: each thread owns one (row, 8k-block): 2xLDG.128 -> 2xSTS.128
// with the kperm interleave applied in-register.
// ---------------------------------------------------------------------------
#define GP 20   // smem row stride (uints)

__global__ __launch_bounds__(256, 2) void gemm_nt_tf32(
    const float* __restrict__ A, const float* __restrict__ B,
    float* __restrict__ C, int M, int N, int K)
{
    __shared__ __align__(16) uint32_t As[2][128 * GP];
    __shared__ __align__(16) uint32_t Bs[2][128 * GP];

    const int tid  = threadIdx.x;
    const int lane = tid & 31;
    const int w    = tid >> 5;
    const int lr   = lane >> 2;
    const int lc   = lane & 3;
    const int wm   = (w >> 2) * 64;
    const int wn   = (w & 3) * 32;
    const int bm   = blockIdx.y * 128;
    const int bn   = blockIdx.x * 128;

    // staging: thread -> (row, k-block): 128 rows x 2 blocks of 8 k's
    const int srow = tid >> 1;            // 0..127
    const int skb  = (tid & 1) * 8;       // 0 or 8
    const float* Aptr = A + ((size_t)(bm + srow)) * K + skb;
    const float* Bptr = B + ((size_t)(bn + srow)) * K + skb;
    uint32_t* AsRow0 = &As[0][srow * GP + skb];
    uint32_t* BsRow0 = &Bs[0][srow * GP + skb];
    uint32_t* AsRow1 = &As[1][srow * GP + skb];
    uint32_t* BsRow1 = &Bs[1][srow * GP + skb];

    float acc[4][4][4] = {};
    float4 au, av, bu, bv;

    // prologue: load k-block 0 and store to buffer 0
    au = *(const float4*)(Aptr);
    av = *(const float4*)(Aptr + 4);
    bu = *(const float4*)(Bptr);
    bv = *(const float4*)(Bptr + 4);
    // kperm interleave: out[0..7] = (u.x,v.x,u.y,v.y,u.z,v.z,u.w,v.w)
    *(uint4*)(AsRow0)     = make_uint4(tf32u(au.x), tf32u(av.x), tf32u(au.y), tf32u(av.y));
    *(uint4*)(AsRow0 + 4) = make_uint4(tf32u(au.z), tf32u(av.z), tf32u(au.w), tf32u(av.w));
    *(uint4*)(BsRow0)     = make_uint4(tf32u(bu.x), tf32u(bv.x), tf32u(bu.y), tf32u(bv.y));
    *(uint4*)(BsRow0 + 4) = make_uint4(tf32u(bu.z), tf32u(bv.z), tf32u(bu.w), tf32u(bv.w));
    __syncthreads();

    const int NIT = K / 16;
    for (int it = 0; it < NIT; it++) {
        const int cur = it & 1;
        const bool more = (it + 1 < NIT);

        if (more) {                      // issue next tile's LDGs early
            const float* An = Aptr + (it + 1) * 16;
            const float* Bn = Bptr + (it + 1) * 16;
            au = *(const float4*)(An);
            av = *(const float4*)(An + 4);
            bu = *(const float4*)(Bn);
            bv = *(const float4*)(Bn + 4);
        }

        const uint32_t* Ac = As[cur];
        const uint32_t* Bc = Bs[cur];
#pragma unroll
        for (int kk = 0; kk < 2; kk++) {
            uint32_t a[4][4];
#pragma unroll
            for (int mt = 0; mt < 4; mt++) {
                int m = wm + mt * 16 + lr;
                uint2 p0 = *(const uint2*)&Ac[m * GP + kk * 8 + lc * 2];
                uint2 p1 = *(const uint2*)&Ac[(m + 8) * GP + kk * 8 + lc * 2];
                a[mt][0] = p0.x; a[mt][2] = p0.y;
                a[mt][1] = p1.x; a[mt][3] = p1.y;
            }
            uint32_t b[4][2];
#pragma unroll
            for (int nt = 0; nt < 4; nt++) {
                int n = wn + nt * 8 + lr;
                uint2 q = *(const uint2*)&Bc[n * GP + kk * 8 + lc * 2];
                b[nt][0] = q.x; b[nt][1] = q.y;
            }
#pragma unroll
            for (int mt = 0; mt < 4; mt++)
#pragma unroll
                for (int nt = 0; nt < 4; nt++)
                    MMA_TF32(acc[mt][nt], a[mt][0], a[mt][1], a[mt][2], a[mt][3],
                             b[nt][0], b[nt][1]);
        }

        if (more) {                      // store next tile into the other buffer
            uint32_t* Ad = cur ? AsRow0 : AsRow1;
            uint32_t* Bd = cur ? BsRow0 : BsRow1;
            *(uint4*)(Ad)     = make_uint4(tf32u(au.x), tf32u(av.x), tf32u(au.y), tf32u(av.y));
            *(uint4*)(Ad + 4) = make_uint4(tf32u(au.z), tf32u(av.z), tf32u(au.w), tf32u(av.w));
            *(uint4*)(Bd)     = make_uint4(tf32u(bu.x), tf32u(bv.x), tf32u(bu.y), tf32u(bv.y));
            *(uint4*)(Bd + 4) = make_uint4(tf32u(bu.z), tf32u(bv.z), tf32u(bu.w), tf32u(bv.w));
        }
        __syncthreads();
    }

    // epilogue
#pragma unroll
    for (int mt = 0; mt < 4; mt++) {
#pragma unroll
        for (int nt = 0; nt < 4; nt++) {
            size_t r = (size_t)(bm + wm + mt * 16 + lr);
            int col = bn + wn + nt * 8 + 2 * lc;
            *(float2*)&C[r * N + col] =
                make_float2(acc[mt][nt][0], acc[mt][nt][1]);
            *(float2*)&C[(r + 8) * N + col] =
                make_float2(acc[mt][nt][2], acc[mt][nt][3]);
        }
    }
}

// ---------------------------------------------------------------------------
// RoPE + head split
// ---------------------------------------------------------------------------
__global__ __launch_bounds__(256) void rope_split_kernel() {
    const int row = blockIdx.x;                  // b*T + t
    const int b = row >> 11;
    const int t = row & (TSEQ - 1);
    const float* src = g_qkv + (size_t)row * (3 * CDIM);

    for (int p = threadIdx.x; p < 3 * CDIM / 2; p += blockDim.x) {
        int col = p * 2;
        int s = col >> 10;                       // 0=q 1=k 2=v
        int within = col & (CDIM - 1);
        int h = within >> 6;
        int j = within & (DH - 1);               // even
        float2 xv = *(const float2*)(src + col);
        size_t dst = (((size_t)(b * NH + h) * TSEQ) + t) * DH + j;
        if (s == 2) {
            *(float2*)(g_Vh + dst) = xv;
        } else {
            float c = g_cosT[t * 32 + (j >> 1)];
            float sn = g_sinT[t * 32 + (j >> 1)];
            float o0 = xv.x * c - xv.y * sn;
            float o1 = xv.y * c + xv.x * sn;
            if (s == 0) {
                o0 *= 0.125f; o1 *= 0.125f;      // 1/sqrt(d_head) folded into Q
                *(float2*)(g_Qh + dst) = make_float2(o0, o1);
            } else {
                *(float2*)(g_Kh + dst) = make_float2(o0, o1);
            }
        }
    }
}

// ---------------------------------------------------------------------------
// Flash attention, tf32 mma. Q tile = 128 rows (8 warps x m16), K tile = 64.
// Q fragments live in registers for the whole kernel. K stored kperm'd
// (LDS.64 B-frags), V stored natural (2x conflict-free LDS.32 B-frags),
// P stored natural (STS.64 / LDS.32). All staging stores are STS.128.
// ---------------------------------------------------------------------------
#define APK 72   // K smem row stride (72 % 32 == 8 -> conflict-free LDS.64)
#define APV 72   // V smem row stride
#define APP 76   // P smem row stride (76 % 32 == 12 -> conflict-free LDS.32)

__global__ __launch_bounds__(256) void attn_tc_kernel() {
    extern __shared__ uint32_t sm[];
    uint32_t* Ks = sm;                  // [64 key][APK]   d kperm'd
    uint32_t* Vs = Ks + 64 * APK;       // [64 key][APV]   natural [key][d]
    uint32_t* Ps = Vs + 64 * APV;       // [128 q][APP]    natural [q][key]

    const int tid  = threadIdx.x;
    const int lane = tid & 31;
    const int w    = tid >> 5;          // warp 0..7 -> q rows w*16..w*16+15
    const int lr   = lane >> 2;
    const int lc   = lane & 3;
    const int iq   = blockIdx.x;        // q tile (128 rows)
    const int bh   = blockIdx.y;

    const float* Qg = g_Qh + ((size_t)bh * TSEQ + iq * 128) * DH;
    const float* Kg = g_Kh + (size_t)bh * TSEQ * DH;
    const float* Vg = g_Vh + (size_t)bh * TSEQ * DH;

    // Q fragments -> registers (reused for every key tile)
    uint32_t qf[8][4];
    {
        const float* q0 = Qg + (w * 16 + lr) * DH;
        const float* q1 = q0 + 8 * DH;
#pragma unroll
        for (int kk = 0; kk < 8; kk++) {
            qf[kk][0] = tf32u(q0[kk * 8 + lc]);
            qf[kk][1] = tf32u(q1[kk * 8 + lc]);
            qf[kk][2] = tf32u(q0[kk * 8 + lc + 4]);
            qf[kk][3] = tf32u(q1[kk * 8 + lc + 4]);
        }
    }

    float oacc[8][4] = {};
    float mrow[2] = {-INFINITY, -INFINITY};
    float lrow[2] = {0.f, 0.f};

    const int NJ = 2 * iq + 2;          // key tiles covering keys <= max row
    for (int j = 0; j < NJ; j++) {
        __syncthreads();                // prior tile's Ks/Vs reads complete
        // ---- stage K (kperm, STS.128) and V (natural, STS.128) ----
        const float* Kt = Kg + (size_t)(j * 64) * DH;
        const float* Vt = Vg + (size_t)(j * 64) * DH;
#pragma unroll
        for (int i = 0; i < 4; i++) {
            int chunk = tid + i * 256;           // 0..1023
            int r = chunk >> 4;
            int c = chunk & 15;
            int b = (c >> 1) << 3;
            int h = c & 1;
            const float* src = Kt + r * DH + b + 2 * h;
            float2 u  = *(const float2*)src;
            float2 v2 = *(const float2*)(src + 4);
            // kperm block [b+4h .. b+4h+3] = (k, k+4, k+1, k+5)
            *(uint4*)&Ks[r * APK + b + 4 * h] =
                make_uint4(tf32u(u.x), tf32u(v2.x), tf32u(u.y), tf32u(v2.y));
            float4 vv = *(const float4*)(Vt + r * DH + c * 4);
            *(uint4*)&Vs[r * APV + c * 4] =
                make_uint4(tf32u(vv.x), tf32u(vv.y), tf32u(vv.z), tf32u(vv.w));
        }
        __syncthreads();

        // ---- S = Q K^T  (m16 x n64, k=64) ----
        float s[8][4] = {};
#pragma unroll
        for (int kk = 0; kk < 8; kk++) {
#pragma unroll
            for (int nt = 0; nt < 8; nt++) {
                uint2 b2 = *(const uint2*)&Ks[(nt * 8 + lr) * APK + kk * 8 + 2 * lc];
                MMA_TF32(s[nt], qf[kk][0], qf[kk][1], qf[kk][2], qf[kk][3],
                         b2.x, b2.y);
            }
        }

        // ---- causal mask (only the last two tiles can be partial) ----
        if (j >= 2 * iq) {
            int rbase = iq * 128 + w * 16 + lr;
            int cbase = j * 64 + 2 * lc;
#pragma unroll
            for (int nt = 0; nt < 8; nt++) {
#pragma unroll
                for (int e = 0; e < 4; e++) {
                    int rl = rbase + (e >> 1) * 8;
                    int cl = cbase + nt * 8 + (e & 1);
                    if (cl > rl) s[nt][e] = -INFINITY;
                }
            }
        }

        // ---- online softmax (per row half) + P store ----
#pragma unroll
        for (int h = 0; h < 2; h++) {
            float mx = -INFINITY;
#pragma unroll
            for (int nt = 0; nt < 8; nt++)
                mx = fmaxf(mx, fmaxf(s[nt][2 * h], s[nt][2 * h + 1]));
            mx = fmaxf(mx, __shfl_xor_sync(0xffffffffu, mx, 1));
            mx = fmaxf(mx, __shfl_xor_sync(0xffffffffu, mx, 2));
            float mnew = fmaxf(mrow[h], mx);
            float alpha = __expf(mrow[h] - mnew);
            float rs = 0.f;
#pragma unroll
            for (int nt = 0; nt < 8; nt++) {
                float p0 = __expf(s[nt][2 * h] - mnew);
                float p1 = __expf(s[nt][2 * h + 1] - mnew);
                s[nt][2 * h] = p0;
                s[nt][2 * h + 1] = p1;
                rs += p0 + p1;
            }
            rs += __shfl_xor_sync(0xffffffffu, rs, 1);
            rs += __shfl_xor_sync(0xffffffffu, rs, 2);
            lrow[h] = lrow[h] * alpha + rs;
            mrow[h] = mnew;
#pragma unroll
            for (int nt = 0; nt < 8; nt++) {
                oacc[nt][2 * h] *= alpha;
                oacc[nt][2 * h + 1] *= alpha;
            }
            int pr = w * 16 + lr + 8 * h;
#pragma unroll
            for (int nt = 0; nt < 8; nt++) {
                *(uint2*)&Ps[pr * APP + nt * 8 + 2 * lc] =
                    make_uint2(tf32u(s[nt][2 * h]), tf32u(s[nt][2 * h + 1]));
            }
        }
        __syncwarp();   // this warp's Ps rows only

        // ---- O += P * V  (m16 x n64, k=64 keys) ----
#pragma unroll
        for (int kk = 0; kk < 8; kk++) {
            int m = w * 16 + lr;
            uint32_t a0 = Ps[m * APP + kk * 8 + lc];
            uint32_t a1 = Ps[(m + 8) * APP + kk * 8 + lc];
            uint32_t a2 = Ps[m * APP + kk * 8 + lc + 4];
            uint32_t a3 = Ps[(m + 8) * APP + kk * 8 + lc + 4];
#pragma unroll
            for (int nt = 0; nt < 8; nt++) {
                uint32_t b0 = Vs[(kk * 8 + lc) * APV + nt * 8 + lr];
                uint32_t b1 = Vs[(kk * 8 + lc + 4) * APV + nt * 8 + lr];
                MMA_TF32(oacc[nt], a0, a1, a2, a3, b0, b1);
            }
        }
    }

    // ---- epilogue: normalize, write [b*T+t][h*64+d] ----
    const int bb = bh >> 4;
    const int hh = bh & 15;
#pragma unroll
    for (int h = 0; h < 2; h++) {
        float inv = 1.f / lrow[h];
        size_t row = (size_t)bb * TSEQ + (size_t)iq * 128 + w * 16 + lr + 8 * h;
        float* dst = g_Oh + row * CDIM + hh * DH;
#pragma unroll
        for (int nt = 0; nt < 8; nt++) {
            int col = nt * 8 + 2 * lc;
            *(float2*)&dst[col] = make_float2(oacc[nt][2 * h] * inv,
                                              oacc[nt][2 * h + 1] * inv);
        }
    }
}

// ---------------------------------------------------------------------------
// Launch
// ---------------------------------------------------------------------------
extern "C" void kernel_launch(void* const* d_in, const int* in_sizes, int n_in,
                              void* d_out, int out_size)
{
    const float* x    = (const float*)d_in[0];
    const float* Wqkv = (const float*)d_in[2];
    const float* Wout = (const float*)d_in[3];
    for (int i = 0; i < n_in; i++) {
        if (in_sizes[i] == BT * CDIM)            x    = (const float*)d_in[i];
        else if (in_sizes[i] == 3 * CDIM * CDIM) Wqkv = (const float*)d_in[i];
        else if (in_sizes[i] == CDIM * CDIM)     Wout = (const float*)d_in[i];
    }
    float* out = (float*)d_out;

    void *p_qkv, *p_oh;
    cudaGetSymbolAddress(&p_qkv, g_qkv);
    cudaGetSymbolAddress(&p_oh, g_Oh);

    const int smem_attn = (64 * APK + 64 * APV + 128 * APP) * (int)sizeof(uint32_t);
    cudaFuncSetAttribute(attn_tc_kernel,
                         cudaFuncAttributeMaxDynamicSharedMemorySize, smem_attn);

    // 1. RoPE tables
    build_tables_kernel<<<(TSEQ * 32 + 255) / 256, 256>>>();

    // 2. QKV = x @ Wqkv^T   [8192 x 3072]
    gemm_nt_tf32<<<dim3(3 * CDIM / 128, BT / 128), 256>>>(
        x, Wqkv, (float*)p_qkv, BT, 3 * CDIM, CDIM);

    // 3. RoPE + split into [bh][t][d]
    rope_split_kernel<<<BT, 256>>>();

    // 4. Flash attention (causal, tf32 tensor cores, 128-row Q tiles)
    attn_tc_kernel<<<dim3(TSEQ / 128, BH), 256, smem_attn>>>();

    // 5. out = attn_out @ Wout^T   [8192 x 1024]
    gemm_nt_tf32<<<dim3(CDIM / 128, BT / 128), 256>>>(
        (const float*)p_oh, Wout, out, BT, CDIM, CDIM);
}

// round 10
// speedup vs baseline: 2.5764x; 1.0637x over previous
#include <cuda_runtime.h>
#include <math.h>
#include <stdint.h>

// Problem constants (fixed by the dataset)
#define BATCH 4
#define TSEQ  2048
#define CDIM  1024
#define NH    16
#define DH    64
#define BT    (BATCH * TSEQ)   // 8192 rows
#define BH    (BATCH * NH)     // 64 (batch*heads)

// ---------------------------------------------------------------------------
// Scratch (device globals; no allocation allowed in kernel_launch)
// ---------------------------------------------------------------------------
__device__ float g_qkv[(size_t)BT * 3 * CDIM];       // 96 MB   x @ Wqkv^T
__device__ float g_Qh[(size_t)BH * TSEQ * DH];       // 32 MB   [bh][t][d], rope'd, *0.125
__device__ float g_Kh[(size_t)BH * TSEQ * DH];       // 32 MB   [bh][t][d], rope'd
__device__ float g_Vh[(size_t)BH * TSEQ * DH];       // 32 MB   [bh][t][d]
__device__ float g_Oh[(size_t)BT * CDIM];            // 32 MB   attention out, [b*T+t][h*64+d]
__device__ float g_cosT[TSEQ * (DH / 2)];            // rope tables
__device__ float g_sinT[TSEQ * (DH / 2)];

// ---------------------------------------------------------------------------
// Helpers
// ---------------------------------------------------------------------------
__device__ __forceinline__ uint32_t tf32u(float x) {
    uint32_t u;
    asm("cvt.rna.tf32.f32 %0, %1;" : "=r"(u) : "f"(x));
    return u;
}

#define MMA_TF32(d, a0, a1, a2, a3, b0, b1)                                  \
    asm volatile(                                                            \
        "mma.sync.aligned.m16n8k8.row.col.f32.tf32.tf32.f32 "                \
        "{%0,%1,%2,%3}, {%4,%5,%6,%7}, {%8,%9}, {%0,%1,%2,%3};"              \
        : "+f"(d[0]), "+f"(d[1]), "+f"(d[2]), "+f"(d[3])                     \
        : "r"(a0), "r"(a1), "r"(a2), "r"(a3), "r"(b0), "r"(b1))

// k-permutation within each 8-wide k-step: k -> (k>>3)*8 + (k&3)*2 + ((k>>2)&1)
// (k, k+4) fragment pairs become adjacent -> LDS.64 per mma operand pair.
__device__ __forceinline__ int kperm(int k) {
    return ((k >> 3) << 3) + ((k & 3) << 1) + ((k >> 2) & 1);
}

// ---------------------------------------------------------------------------
// RoPE tables
// ---------------------------------------------------------------------------
__global__ void build_tables_kernel() {
    int idx = blockIdx.x * blockDim.x + threadIdx.x;     // t*32 + i
    if (idx >= TSEQ * (DH / 2)) return;
    int t = idx >> 5;
    int i = idx & 31;
    float theta_f = (float)pow(10000.0, -(double)(2 * i) / (double)DH);
    float angle_f = (float)t * theta_f;
    g_cosT[idx] = (float)cos((double)angle_f);
    g_sinT[idx] = (float)sin((double)angle_f);
}

// ---------------------------------------------------------------------------
// NT GEMM via tf32 mma.sync: C[M,N] = A[M,K] * B[N,K]^T, row-major.
// Block tile 256x128, BK=16, 256 threads = 8 warps (4x2), warp tile 64x64.
// Per kk-step: 32 mmas on 16 LDS.64 per warp (0.5 LDS.64/mma).
// Double-buffered dynamic smem (60 KB), one __syncthreads per iteration.
// M%256==0, N%128==0, K%16==0 for every call here.
// ---------------------------------------------------------------------------
#define GP 20   // smem row stride (uints)

__global__ __launch_bounds__(256) void gemm_nt_tf32(
    const float* __restrict__ A, const float* __restrict__ B,
    float* __restrict__ C, int M, int N, int K)
{
    extern __shared__ __align__(16) uint32_t gsm[];
    uint32_t* As = gsm;                    // [2][256*GP]
    uint32_t* Bs = gsm + 2 * 256 * GP;     // [2][128*GP]

    const int tid  = threadIdx.x;
    const int lane = tid & 31;
    const int w    = tid >> 5;
    const int lr   = lane >> 2;
    const int lc   = lane & 3;
    const int wm   = (w >> 1) * 64;        // 4 m-positions
    const int wn   = (w & 1) * 64;         // 2 n-positions
    const int bm   = blockIdx.y * 256;
    const int bn   = blockIdx.x * 128;

    // staging: A has 512 chunks (256 rows x 2 k-blocks), 2 per thread;
    //          B has 256 chunks (128 rows x 2 k-blocks), 1 per thread.
    const int ar0 = tid >> 1,        ak0 = (tid & 1) * 8;
    const int ar1 = (tid + 256) >> 1, ak1 = ((tid + 256) & 1) * 8;
    const int br_ = tid >> 1,        bk_ = (tid & 1) * 8;

    const float* Ap0 = A + (size_t)(bm + ar0) * K + ak0;
    const float* Ap1 = A + (size_t)(bm + ar1) * K + ak1;
    const float* Bp  = B + (size_t)(bn + br_) * K + bk_;
    uint32_t* AsD0 = As + ar0 * GP + ak0;
    uint32_t* AsD1 = As + ar1 * GP + ak1;
    uint32_t* BsD  = Bs + br_ * GP + bk_;
    const int ABUF = 256 * GP;             // A buffer stride
    const int BBUF = 128 * GP;             // B buffer stride

    float acc[4][8][4] = {};
    float4 a0u, a0v, a1u, a1v, bu, bv;

    // prologue: k-block 0 -> buffer 0
    a0u = *(const float4*)(Ap0);  a0v = *(const float4*)(Ap0 + 4);
    a1u = *(const float4*)(Ap1);  a1v = *(const float4*)(Ap1 + 4);
    bu  = *(const float4*)(Bp);   bv  = *(const float4*)(Bp + 4);
    *(uint4*)(AsD0)     = make_uint4(tf32u(a0u.x), tf32u(a0v.x), tf32u(a0u.y), tf32u(a0v.y));
    *(uint4*)(AsD0 + 4) = make_uint4(tf32u(a0u.z), tf32u(a0v.z), tf32u(a0u.w), tf32u(a0v.w));
    *(uint4*)(AsD1)     = make_uint4(tf32u(a1u.x), tf32u(a1v.x), tf32u(a1u.y), tf32u(a1v.y));
    *(uint4*)(AsD1 + 4) = make_uint4(tf32u(a1u.z), tf32u(a1v.z), tf32u(a1u.w), tf32u(a1v.w));
    *(uint4*)(BsD)      = make_uint4(tf32u(bu.x),  tf32u(bv.x),  tf32u(bu.y),  tf32u(bv.y));
    *(uint4*)(BsD + 4)  = make_uint4(tf32u(bu.z),  tf32u(bv.z),  tf32u(bu.w),  tf32u(bv.w));
    __syncthreads();

    const int NIT = K / 16;
    for (int it = 0; it < NIT; it++) {
        const int cur = it & 1;
        const bool more = (it + 1 < NIT);

        if (more) {
            int k0 = (it + 1) * 16;
            a0u = *(const float4*)(Ap0 + k0);  a0v = *(const float4*)(Ap0 + k0 + 4);
            a1u = *(const float4*)(Ap1 + k0);  a1v = *(const float4*)(Ap1 + k0 + 4);
            bu  = *(const float4*)(Bp + k0);   bv  = *(const float4*)(Bp + k0 + 4);
        }

        const uint32_t* Ac = As + cur * ABUF;
        const uint32_t* Bc = Bs + cur * BBUF;
#pragma unroll
        for (int kk = 0; kk < 2; kk++) {
            uint32_t a[4][4];
#pragma unroll
            for (int mt = 0; mt < 4; mt++) {
                int m = wm + mt * 16 + lr;
                uint2 p0 = *(const uint2*)&Ac[m * GP + kk * 8 + lc * 2];
                uint2 p1 = *(const uint2*)&Ac[(m + 8) * GP + kk * 8 + lc * 2];
                a[mt][0] = p0.x; a[mt][2] = p0.y;
                a[mt][1] = p1.x; a[mt][3] = p1.y;
            }
            uint32_t b[8][2];
#pragma unroll
            for (int nt = 0; nt < 8; nt++) {
                int n = wn + nt * 8 + lr;
                uint2 q = *(const uint2*)&Bc[n * GP + kk * 8 + lc * 2];
                b[nt][0] = q.x; b[nt][1] = q.y;
            }
#pragma unroll
            for (int mt = 0; mt < 4; mt++)
#pragma unroll
                for (int nt = 0; nt < 8; nt++)
                    MMA_TF32(acc[mt][nt], a[mt][0], a[mt][1], a[mt][2], a[mt][3],
                             b[nt][0], b[nt][1]);
        }

        if (more) {
            uint32_t* Ad0 = AsD0 + (cur ^ 1) * ABUF;
            uint32_t* Ad1 = AsD1 + (cur ^ 1) * ABUF;
            uint32_t* Bd  = BsD  + (cur ^ 1) * BBUF;
            *(uint4*)(Ad0)     = make_uint4(tf32u(a0u.x), tf32u(a0v.x), tf32u(a0u.y), tf32u(a0v.y));
            *(uint4*)(Ad0 + 4) = make_uint4(tf32u(a0u.z), tf32u(a0v.z), tf32u(a0u.w), tf32u(a0v.w));
            *(uint4*)(Ad1)     = make_uint4(tf32u(a1u.x), tf32u(a1v.x), tf32u(a1u.y), tf32u(a1v.y));
            *(uint4*)(Ad1 + 4) = make_uint4(tf32u(a1u.z), tf32u(a1v.z), tf32u(a1u.w), tf32u(a1v.w));
            *(uint4*)(Bd)      = make_uint4(tf32u(bu.x),  tf32u(bv.x),  tf32u(bu.y),  tf32u(bv.y));
            *(uint4*)(Bd + 4)  = make_uint4(tf32u(bu.z),  tf32u(bv.z),  tf32u(bu.w),  tf32u(bv.w));
        }
        __syncthreads();
    }

    // epilogue
#pragma unroll
    for (int mt = 0; mt < 4; mt++) {
#pragma unroll
        for (int nt = 0; nt < 8; nt++) {
            size_t r = (size_t)(bm + wm + mt * 16 + lr);
            int col = bn + wn + nt * 8 + 2 * lc;
            *(float2*)&C[r * N + col] =
                make_float2(acc[mt][nt][0], acc[mt][nt][1]);
            *(float2*)&C[(r + 8) * N + col] =
                make_float2(acc[mt][nt][2], acc[mt][nt][3]);
        }
    }
}

#define GEMM_SMEM ((2 * 256 * GP + 2 * 128 * GP) * (int)sizeof(uint32_t))  // 61440 B

// ---------------------------------------------------------------------------
// RoPE + head split
// ---------------------------------------------------------------------------
__global__ __launch_bounds__(256) void rope_split_kernel() {
    const int row = blockIdx.x;                  // b*T + t
    const int b = row >> 11;
    const int t = row & (TSEQ - 1);
    const float* src = g_qkv + (size_t)row * (3 * CDIM);

    for (int p = threadIdx.x; p < 3 * CDIM / 2; p += blockDim.x) {
        int col = p * 2;
        int s = col >> 10;                       // 0=q 1=k 2=v
        int within = col & (CDIM - 1);
        int h = within >> 6;
        int j = within & (DH - 1);               // even
        float2 xv = *(const float2*)(src + col);
        size_t dst = (((size_t)(b * NH + h) * TSEQ) + t) * DH + j;
        if (s == 2) {
            *(float2*)(g_Vh + dst) = xv;
        } else {
            float c = g_cosT[t * 32 + (j >> 1)];
            float sn = g_sinT[t * 32 + (j >> 1)];
            float o0 = xv.x * c - xv.y * sn;
            float o1 = xv.y * c + xv.x * sn;
            if (s == 0) {
                o0 *= 0.125f; o1 *= 0.125f;      // 1/sqrt(d_head) folded into Q
                *(float2*)(g_Qh + dst) = make_float2(o0, o1);
            } else {
                *(float2*)(g_Kh + dst) = make_float2(o0, o1);
            }
        }
    }
}

// ---------------------------------------------------------------------------
// Flash attention, tf32 mma. Q tile = 128 rows (8 warps x m16), K tile = 64.
// (unchanged from R7/R9 for attribution)
// ---------------------------------------------------------------------------
#define APK 72   // K smem row stride (72 % 32 == 8 -> conflict-free LDS.64)
#define APV 72   // V smem row stride
#define APP 76   // P smem row stride (76 % 32 == 12 -> conflict-free LDS.32)

__global__ __launch_bounds__(256) void attn_tc_kernel() {
    extern __shared__ uint32_t sm[];
    uint32_t* Ks = sm;                  // [64 key][APK]   d kperm'd
    uint32_t* Vs = Ks + 64 * APK;       // [64 key][APV]   natural [key][d]
    uint32_t* Ps = Vs + 64 * APV;       // [128 q][APP]    natural [q][key]

    const int tid  = threadIdx.x;
    const int lane = tid & 31;
    const int w    = tid >> 5;          // warp 0..7 -> q rows w*16..w*16+15
    const int lr   = lane >> 2;
    const int lc   = lane & 3;
    const int iq   = blockIdx.x;        // q tile (128 rows)
    const int bh   = blockIdx.y;

    const float* Qg = g_Qh + ((size_t)bh * TSEQ + iq * 128) * DH;
    const float* Kg = g_Kh + (size_t)bh * TSEQ * DH;
    const float* Vg = g_Vh + (size_t)bh * TSEQ * DH;

    // Q fragments -> registers (reused for every key tile)
    uint32_t qf[8][4];
    {
        const float* q0 = Qg + (w * 16 + lr) * DH;
        const float* q1 = q0 + 8 * DH;
#pragma unroll
        for (int kk = 0; kk < 8; kk++) {
            qf[kk][0] = tf32u(q0[kk * 8 + lc]);
            qf[kk][1] = tf32u(q1[kk * 8 + lc]);
            qf[kk][2] = tf32u(q0[kk * 8 + lc + 4]);
            qf[kk][3] = tf32u(q1[kk * 8 + lc + 4]);
        }
    }

    float oacc[8][4] = {};
    float mrow[2] = {-INFINITY, -INFINITY};
    float lrow[2] = {0.f, 0.f};

    const int NJ = 2 * iq + 2;          // key tiles covering keys <= max row
    for (int j = 0; j < NJ; j++) {
        __syncthreads();                // prior tile's Ks/Vs reads complete
        // ---- stage K (kperm, STS.128) and V (natural, STS.128) ----
        const float* Kt = Kg + (size_t)(j * 64) * DH;
        const float* Vt = Vg + (size_t)(j * 64) * DH;
#pragma unroll
        for (int i = 0; i < 4; i++) {
            int chunk = tid + i * 256;           // 0..1023
            int r = chunk >> 4;
            int c = chunk & 15;
            int b = (c >> 1) << 3;
            int h = c & 1;
            const float* src = Kt + r * DH + b + 2 * h;
            float2 u  = *(const float2*)src;
            float2 v2 = *(const float2*)(src + 4);
            // kperm block [b+4h .. b+4h+3] = (k, k+4, k+1, k+5)
            *(uint4*)&Ks[r * APK + b + 4 * h] =
                make_uint4(tf32u(u.x), tf32u(v2.x), tf32u(u.y), tf32u(v2.y));
            float4 vv = *(const float4*)(Vt + r * DH + c * 4);
            *(uint4*)&Vs[r * APV + c * 4] =
                make_uint4(tf32u(vv.x), tf32u(vv.y), tf32u(vv.z), tf32u(vv.w));
        }
        __syncthreads();

        // ---- S = Q K^T  (m16 x n64, k=64) ----
        float s[8][4] = {};
#pragma unroll
        for (int kk = 0; kk < 8; kk++) {
#pragma unroll
            for (int nt = 0; nt < 8; nt++) {
                uint2 b2 = *(const uint2*)&Ks[(nt * 8 + lr) * APK + kk * 8 + 2 * lc];
                MMA_TF32(s[nt], qf[kk][0], qf[kk][1], qf[kk][2], qf[kk][3],
                         b2.x, b2.y);
            }
        }

        // ---- causal mask (only the last two tiles can be partial) ----
        if (j >= 2 * iq) {
            int rbase = iq * 128 + w * 16 + lr;
            int cbase = j * 64 + 2 * lc;
#pragma unroll
            for (int nt = 0; nt < 8; nt++) {
#pragma unroll
                for (int e = 0; e < 4; e++) {
                    int rl = rbase + (e >> 1) * 8;
                    int cl = cbase + nt * 8 + (e & 1);
                    if (cl > rl) s[nt][e] = -INFINITY;
                }
            }
        }

        // ---- online softmax (per row half) + P store ----
#pragma unroll
        for (int h = 0; h < 2; h++) {
            float mx = -INFINITY;
#pragma unroll
            for (int nt = 0; nt < 8; nt++)
                mx = fmaxf(mx, fmaxf(s[nt][2 * h], s[nt][2 * h + 1]));
            mx = fmaxf(mx, __shfl_xor_sync(0xffffffffu, mx, 1));
            mx = fmaxf(mx, __shfl_xor_sync(0xffffffffu, mx, 2));
            float mnew = fmaxf(mrow[h], mx);
            float alpha = __expf(mrow[h] - mnew);
            float rs = 0.f;
#pragma unroll
            for (int nt = 0; nt < 8; nt++) {
                float p0 = __expf(s[nt][2 * h] - mnew);
                float p1 = __expf(s[nt][2 * h + 1] - mnew);
                s[nt][2 * h] = p0;
                s[nt][2 * h + 1] = p1;
                rs += p0 + p1;
            }
            rs += __shfl_xor_sync(0xffffffffu, rs, 1);
            rs += __shfl_xor_sync(0xffffffffu, rs, 2);
            lrow[h] = lrow[h] * alpha + rs;
            mrow[h] = mnew;
#pragma unroll
            for (int nt = 0; nt < 8; nt++) {
                oacc[nt][2 * h] *= alpha;
                oacc[nt][2 * h + 1] *= alpha;
            }
            int pr = w * 16 + lr + 8 * h;
#pragma unroll
            for (int nt = 0; nt < 8; nt++) {
                *(uint2*)&Ps[pr * APP + nt * 8 + 2 * lc] =
                    make_uint2(tf32u(s[nt][2 * h]), tf32u(s[nt][2 * h + 1]));
            }
        }
        __syncwarp();   // this warp's Ps rows only

        // ---- O += P * V  (m16 x n64, k=64 keys) ----
#pragma unroll
        for (int kk = 0; kk < 8; kk++) {
            int m = w * 16 + lr;
            uint32_t a0 = Ps[m * APP + kk * 8 + lc];
            uint32_t a1 = Ps[(m + 8) * APP + kk * 8 + lc];
            uint32_t a2 = Ps[m * APP + kk * 8 + lc + 4];
            uint32_t a3 = Ps[(m + 8) * APP + kk * 8 + lc + 4];
#pragma unroll
            for (int nt = 0; nt < 8; nt++) {
                uint32_t b0 = Vs[(kk * 8 + lc) * APV + nt * 8 + lr];
                uint32_t b1 = Vs[(kk * 8 + lc + 4) * APV + nt * 8 + lr];
                MMA_TF32(oacc[nt], a0, a1, a2, a3, b0, b1);
            }
        }
    }

    // ---- epilogue: normalize, write [b*T+t][h*64+d] ----
    const int bb = bh >> 4;
    const int hh = bh & 15;
#pragma unroll
    for (int h = 0; h < 2; h++) {
        float inv = 1.f / lrow[h];
        size_t row = (size_t)bb * TSEQ + (size_t)iq * 128 + w * 16 + lr + 8 * h;
        float* dst = g_Oh + row * CDIM + hh * DH;
#pragma unroll
        for (int nt = 0; nt < 8; nt++) {
            int col = nt * 8 + 2 * lc;
            *(float2*)&dst[col] = make_float2(oacc[nt][2 * h] * inv,
                                              oacc[nt][2 * h + 1] * inv);
        }
    }
}

// ---------------------------------------------------------------------------
// Launch
// ---------------------------------------------------------------------------
extern "C" void kernel_launch(void* const* d_in, const int* in_sizes, int n_in,
                              void* d_out, int out_size)
{
    const float* x    = (const float*)d_in[0];
    const float* Wqkv = (const float*)d_in[2];
    const float* Wout = (const float*)d_in[3];
    for (int i = 0; i < n_in; i++) {
        if (in_sizes[i] == BT * CDIM)            x    = (const float*)d_in[i];
        else if (in_sizes[i] == 3 * CDIM * CDIM) Wqkv = (const float*)d_in[i];
        else if (in_sizes[i] == CDIM * CDIM)     Wout = (const float*)d_in[i];
    }
    float* out = (float*)d_out;

    void *p_qkv, *p_oh;
    cudaGetSymbolAddress(&p_qkv, g_qkv);
    cudaGetSymbolAddress(&p_oh, g_Oh);

    const int smem_attn = (64 * APK + 64 * APV + 128 * APP) * (int)sizeof(uint32_t);
    cudaFuncSetAttribute(attn_tc_kernel,
                         cudaFuncAttributeMaxDynamicSharedMemorySize, smem_attn);
    cudaFuncSetAttribute(gemm_nt_tf32,
                         cudaFuncAttributeMaxDynamicSharedMemorySize, GEMM_SMEM);

    // 1. RoPE tables
    build_tables_kernel<<<(TSEQ * 32 + 255) / 256, 256>>>();

    // 2. QKV = x @ Wqkv^T   [8192 x 3072]
    gemm_nt_tf32<<<dim3(3 * CDIM / 128, BT / 256), 256, GEMM_SMEM>>>(
        x, Wqkv, (float*)p_qkv, BT, 3 * CDIM, CDIM);

    // 3. RoPE + split into [bh][t][d]
    rope_split_kernel<<<BT, 256>>>();

    // 4. Flash attention (causal, tf32 tensor cores, 128-row Q tiles)
    attn_tc_kernel<<<dim3(TSEQ / 128, BH), 256, smem_attn>>>();

    // 5. out = attn_out @ Wout^T   [8192 x 1024]
    gemm_nt_tf32<<<dim3(CDIM / 128, BT / 256), 256, GEMM_SMEM>>>(
        (const float*)p_oh, Wout, out, BT, CDIM, CDIM);
}